// round 15
// baseline (speedup 1.0000x reference)
#include <cuda_runtime.h>
#include <cuda_bf16.h>
#include <cstdint>

#define N_NODES 50000
#define C 128
#define C4 32        // float4 per row
#define E_CAP 600064

// ---------------- device scratch (no allocs allowed) ----------------
__device__ __align__(16) float g_agg[(size_t)N_NODES * C];  // mean after agg
__device__ __align__(16) float g_h[(size_t)N_NODES * C];
__device__ __align__(16) float g_inv[N_NODES];
__device__ __align__(16) int   g_cnt[N_NODES];
__device__ __align__(16) int   g_row[N_NODES + 4];
__device__ __align__(16) int   g_cur[N_NODES];
__device__ int g_csr[E_CAP];
__device__ int g_not64 = 0;   // idempotent: set iff int32 evidence found
// preconverted split-bf16 weights: order Wl1, Wr1, Wl2, Wr2
__device__ __align__(16) uint16_t g_wh[4][C * C];
__device__ __align__(16) uint16_t g_wl[4][C * C];
// multi-block scan scratch
#define NCH 12500                 // 50000 / 4 int4 chunks
#define SCAN_BLK 256
#define SCAN_NB ((NCH + SCAN_BLK - 1) / SCAN_BLK)   // 49
__device__ int g_bsum[SCAN_NB];
__device__ int g_boff[SCAN_NB];

__device__ __forceinline__ uint32_t pack_bf(float a, float b) {
    __nv_bfloat162 h = __floats2bfloat162_rn(a, b);  // .x = a (low half)
    return *(uint32_t*)&h;
}

// ============= zero counts + dtype detect =============
__global__ void detect_init_kernel(const unsigned int* __restrict__ w, int nwords) {
    int i = blockIdx.x * blockDim.x + threadIdx.x;
    if (i < N_NODES) g_cnt[i] = 0;
    int wi = 2 * i + 1;
    if (wi < nwords && w[wi] != 0u) g_not64 = 1;
}

// ============= histogram of dst (4 edges/thread, ILP) =============
__global__ void count_kernel(const void* __restrict__ ei, int E) {
    int base = (blockIdx.x * blockDim.x + threadIdx.x) * 4;
    if (base >= E) return;
    int d[4];
    int n = E - base; if (n > 4) n = 4;
    if (g_not64 == 0) {
        const long long* p = (const long long*)ei;
#pragma unroll
        for (int q = 0; q < 4; q++)
            if (q < n) d[q] = (int)p[(long long)E + base + q];
    } else {
        const int* p = (const int*)ei;
#pragma unroll
        for (int q = 0; q < 4; q++)
            if (q < n) d[q] = p[E + base + q];
    }
#pragma unroll
    for (int q = 0; q < 4; q++)
        if (q < n) atomicAdd(&g_cnt[d[q]], 1);
}

// ============= scan A/B/C =============
__global__ __launch_bounds__(SCAN_BLK)
void scanA_kernel() {
    __shared__ int warp_tot[8];
    int tid  = threadIdx.x;
    int lane = tid & 31;
    int wid  = tid >> 5;
    int i = blockIdx.x * SCAN_BLK + tid;
    int4 c = (i < NCH) ? ((const int4*)g_cnt)[i] : make_int4(0, 0, 0, 0);
    int s = c.x + c.y + c.z + c.w;
    int x = s;
#pragma unroll
    for (int off = 1; off < 32; off <<= 1) {
        int y = __shfl_up_sync(0xffffffffu, x, off);
        if (lane >= off) x += y;
    }
    if (lane == 31) warp_tot[wid] = x;
    __syncthreads();
    if (wid == 0 && lane < 8) {
        int t = warp_tot[lane];
        int tx = t;
#pragma unroll
        for (int off = 1; off < 8; off <<= 1) {
            int y = __shfl_up_sync(0xffu, tx, off);
            if (lane >= off) tx += y;
        }
        warp_tot[lane] = tx - t;
    }
    __syncthreads();
    int excl = warp_tot[wid] + x - s;
    if (i < NCH) {
        int4 r;
        r.x = excl;
        r.y = excl + c.x;
        r.z = r.y + c.y;
        r.w = r.z + c.z;
        ((int4*)g_row)[i] = r;
        float4 f;
        f.x = 1.0f / fmaxf((float)c.x, 1.0f);
        f.y = 1.0f / fmaxf((float)c.y, 1.0f);
        f.z = 1.0f / fmaxf((float)c.z, 1.0f);
        f.w = 1.0f / fmaxf((float)c.w, 1.0f);
        ((float4*)g_inv)[i] = f;
    }
    if (tid == SCAN_BLK - 1) g_bsum[blockIdx.x] = excl + s;
}

__global__ void scanB_kernel() {
    __shared__ int sh[2];
    int tid = threadIdx.x;  // 64
    int v = (tid < SCAN_NB) ? g_bsum[tid] : 0;
    int lane = tid & 31, w = tid >> 5;
    int x = v;
#pragma unroll
    for (int off = 1; off < 32; off <<= 1) {
        int y = __shfl_up_sync(0xffffffffu, x, off);
        if (lane >= off) x += y;
    }
    if (lane == 31) sh[w] = x;
    __syncthreads();
    int carry = (w == 1) ? sh[0] : 0;
    int excl = carry + x - v;
    if (tid < SCAN_NB) g_boff[tid] = excl;
    if (tid == SCAN_NB - 1) g_row[N_NODES] = excl + v;
}

__global__ __launch_bounds__(SCAN_BLK)
void scanC_kernel() {
    int i = blockIdx.x * SCAN_BLK + threadIdx.x;
    if (i >= NCH) return;
    int off = g_boff[blockIdx.x];
    int4 r = ((const int4*)g_row)[i];
    r.x += off; r.y += off; r.z += off; r.w += off;
    ((int4*)g_row)[i] = r;
    ((int4*)g_cur)[i] = r;
}

// ============= fill CSR (4 edges/thread, ILP) =============
__global__ void fill_kernel(const void* __restrict__ ei, int E) {
    int base = (blockIdx.x * blockDim.x + threadIdx.x) * 4;
    if (base >= E) return;
    int n = E - base; if (n > 4) n = 4;
    int s[4], d[4];
    if (g_not64 == 0) {
        const long long* p = (const long long*)ei;
#pragma unroll
        for (int q = 0; q < 4; q++)
            if (q < n) {
                s[q] = (int)p[base + q];
                d[q] = (int)p[(long long)E + base + q];
            }
    } else {
        const int* p = (const int*)ei;
#pragma unroll
        for (int q = 0; q < 4; q++)
            if (q < n) {
                s[q] = p[base + q];
                d[q] = p[E + base + q];
            }
    }
    int pos[4];
#pragma unroll
    for (int q = 0; q < 4; q++)
        if (q < n) pos[q] = atomicAdd(&g_cur[d[q]], 1);
#pragma unroll
    for (int q = 0; q < 4; q++)
        if (q < n) g_csr[pos[q]] = s[q];
}

// ============= weight prep: fp32 -> split bf16 =============
__global__ void wprep_kernel(const float* __restrict__ W0, const float* __restrict__ W1,
                             const float* __restrict__ W2, const float* __restrict__ W3) {
    int i = blockIdx.x * blockDim.x + threadIdx.x;
    if (i >= 4 * (C * C / 4)) return;
    int m = i >> 12;
    int q = i & 4095;
    const float* W = (m == 0) ? W0 : (m == 1) ? W1 : (m == 2) ? W2 : W3;
    float4 v = ((const float4*)W)[q];
    float hx = __bfloat162float(__float2bfloat16_rn(v.x));
    float hy = __bfloat162float(__float2bfloat16_rn(v.y));
    float hz = __bfloat162float(__float2bfloat16_rn(v.z));
    float hw = __bfloat162float(__float2bfloat16_rn(v.w));
    *(uint2*)&g_wh[m][q * 4] = make_uint2(pack_bf(hx, hy), pack_bf(hz, hw));
    *(uint2*)&g_wl[m][q * 4] = make_uint2(pack_bf(v.x - hx, v.y - hy),
                                          pack_bf(v.z - hz, v.w - hw));
}

// ============= mean aggregation (gather, no atomics) =============
__global__ __launch_bounds__(256)
void agg_kernel(const float* __restrict__ feat_in, int feat_is_gh) {
    const float* feat = feat_is_gh ? (const float*)g_h : feat_in;
    int gt   = blockIdx.x * blockDim.x + threadIdx.x;
    int node = gt >> 5;
    int lane = gt & 31;
    if (node >= N_NODES) return;
    int beg = g_row[node];
    int end = g_row[node + 1];
    const float4* f4 = (const float4*)feat;
    float4 acc = make_float4(0.f, 0.f, 0.f, 0.f);
    int i = beg;
    for (; i + 4 <= end; i += 4) {
        int s0 = g_csr[i + 0];
        int s1 = g_csr[i + 1];
        int s2 = g_csr[i + 2];
        int s3 = g_csr[i + 3];
        float4 v0 = f4[(size_t)s0 * C4 + lane];
        float4 v1 = f4[(size_t)s1 * C4 + lane];
        float4 v2 = f4[(size_t)s2 * C4 + lane];
        float4 v3 = f4[(size_t)s3 * C4 + lane];
        acc.x += v0.x + v1.x + v2.x + v3.x;
        acc.y += v0.y + v1.y + v2.y + v3.y;
        acc.z += v0.z + v1.z + v2.z + v3.z;
        acc.w += v0.w + v1.w + v2.w + v3.w;
    }
    for (; i < end; i++) {
        float4 v = f4[(size_t)g_csr[i] * C4 + lane];
        acc.x += v.x; acc.y += v.y; acc.z += v.z; acc.w += v.w;
    }
    float inv = g_inv[node];
    acc.x *= inv; acc.y *= inv; acc.z *= inv; acc.w *= inv;
    ((float4*)g_agg)[(size_t)node * C4 + lane] = acc;
}

// ============= bf16-split half-layer GEMM via mma.sync =============
// O [+]= A @ W[widx]^T [+ bias] [relu].  a_sel: 0=Ain, 1=g_agg, 2=g_h.
// 4 K-chunks of 32 over C=128.  D += Ah*Bh + Ah*Bl + Al*Bh (fp32 accum).
#define SA 40   // padded row length (bf16 elems) for 128x32 tiles

__device__ __forceinline__ uint32_t smem_u32(const void* p) {
    uint32_t a;
    asm("{ .reg .u64 t; cvta.to.shared.u64 t, %1; cvt.u32.u64 %0, t; }"
        : "=r"(a) : "l"(p));
    return a;
}

__device__ __forceinline__ void ldm_x4(uint32_t* r, uint32_t addr) {
    asm volatile("ldmatrix.sync.aligned.m8n8.x4.shared.b16 {%0,%1,%2,%3}, [%4];"
                 : "=r"(r[0]), "=r"(r[1]), "=r"(r[2]), "=r"(r[3]) : "r"(addr));
}

__device__ __forceinline__ void mma_bf16(float* d, const uint32_t* a,
                                         uint32_t b0, uint32_t b1) {
    asm volatile(
        "mma.sync.aligned.m16n8k16.row.col.f32.bf16.bf16.f32 "
        "{%0,%1,%2,%3}, {%4,%5,%6,%7}, {%8,%9}, {%0,%1,%2,%3};"
        : "+f"(d[0]), "+f"(d[1]), "+f"(d[2]), "+f"(d[3])
        : "r"(a[0]), "r"(a[1]), "r"(a[2]), "r"(a[3]), "r"(b0), "r"(b1));
}

__global__ __launch_bounds__(256)
void hmma_half(const float* __restrict__ Ain, int a_sel, int widx,
               const float* __restrict__ bias,
               float* __restrict__ Oin, int o_is_gh, int add_prev, int relu) {
    __shared__ __align__(16) uint16_t sAh[128 * SA];
    __shared__ __align__(16) uint16_t sAl[128 * SA];
    __shared__ __align__(16) uint16_t sBh[128 * SA];
    __shared__ __align__(16) uint16_t sBl[128 * SA];

    const float* A = (a_sel == 1) ? (const float*)g_agg
                   : (a_sel == 2) ? (const float*)g_h
                   : Ain;
    float* O = o_is_gh ? (float*)g_h : Oin;

    int t    = threadIdx.x;
    int w    = t >> 5;
    int lane = t & 31;
    int mw   = (w & 3) * 32;
    int nw   = (w >> 2) * 64;
    long long bm = (long long)blockIdx.x * 128;

    float acc[2][8][4];
#pragma unroll
    for (int i = 0; i < 2; i++)
#pragma unroll
        for (int j = 0; j < 8; j++)
#pragma unroll
            for (int q = 0; q < 4; q++) acc[i][j][q] = 0.f;

    uint32_t aAh = smem_u32(sAh), aAl = smem_u32(sAl);
    uint32_t aBh = smem_u32(sBh), aBl = smem_u32(sBl);

    int lrow = t >> 1;
    int lhk  = t & 1;
    long long arow = bm + lrow;
    if (arow >= N_NODES) arow = N_NODES - 1;
    int cbase = lrow * SA + lhk * 16;
    const float4* A4 = (const float4*)A;

#pragma unroll 1
    for (int chunk = 0; chunk < 4; chunk++) {
        int k0 = chunk * 32;

        // ---- A: load fp32, split-convert to smem ----
        const float4* pa = A4 + arow * C4 + (k0 >> 2) + lhk * 4;
#pragma unroll
        for (int q = 0; q < 4; q++) {
            float4 v = pa[q];
            float hx = __bfloat162float(__float2bfloat16_rn(v.x));
            float hy = __bfloat162float(__float2bfloat16_rn(v.y));
            float hz = __bfloat162float(__float2bfloat16_rn(v.z));
            float hw = __bfloat162float(__float2bfloat16_rn(v.w));
            *(uint32_t*)&sAh[cbase + q * 4]     = pack_bf(hx, hy);
            *(uint32_t*)&sAh[cbase + q * 4 + 2] = pack_bf(hz, hw);
            *(uint32_t*)&sAl[cbase + q * 4]     = pack_bf(v.x - hx, v.y - hy);
            *(uint32_t*)&sAl[cbase + q * 4 + 2] = pack_bf(v.z - hz, v.w - hw);
        }
        // ---- B: bf16 copies from preconverted weights ----
        {
            const uint4* ph = (const uint4*)&g_wh[widx][lrow * C + k0 + lhk * 16];
            const uint4* pl = (const uint4*)&g_wl[widx][lrow * C + k0 + lhk * 16];
            *(uint4*)&sBh[cbase]     = ph[0];
            *(uint4*)&sBh[cbase + 8] = ph[1];
            *(uint4*)&sBl[cbase]     = pl[0];
            *(uint4*)&sBl[cbase + 8] = pl[1];
        }
        __syncthreads();

#pragma unroll
        for (int k16 = 0; k16 < 2; k16++) {
            int kb = k16 * 16;
            uint32_t ah[2][4], al[2][4];
#pragma unroll
            for (int mt = 0; mt < 2; mt++) {
                int off = ((mw + mt * 16 + (lane & 15)) * SA
                           + kb + (lane >> 4) * 8) * 2;
                ldm_x4(ah[mt], aAh + off);
                ldm_x4(al[mt], aAl + off);
            }
            uint32_t bh[4][4], bl[4][4];
#pragma unroll
            for (int g = 0; g < 4; g++) {
                int row = nw + g * 16 + (lane & 7) + ((lane >> 3) & 1) * 8;
                int col = kb + ((lane >> 4) & 1) * 8;
                int off = (row * SA + col) * 2;
                ldm_x4(bh[g], aBh + off);
                ldm_x4(bl[g], aBl + off);
            }
#pragma unroll
            for (int mt = 0; mt < 2; mt++) {
#pragma unroll
                for (int nt = 0; nt < 8; nt++) {
                    int g = nt >> 1, s = nt & 1;
                    uint32_t bh0 = bh[g][s], bh1 = bh[g][s + 2];
                    uint32_t bl0 = bl[g][s], bl1 = bl[g][s + 2];
                    mma_bf16(acc[mt][nt], ah[mt], bh0, bh1);
                    mma_bf16(acc[mt][nt], ah[mt], bl0, bl1);
                    mma_bf16(acc[mt][nt], al[mt], bh0, bh1);
                }
            }
        }
        __syncthreads();
    }

    // ---- epilogue ----
    int crow = lane >> 2;
    int ccol = (lane & 3) * 2;
#pragma unroll
    for (int mt = 0; mt < 2; mt++) {
        long long r0 = bm + mw + mt * 16 + crow;
        long long r1 = r0 + 8;
#pragma unroll
        for (int nt = 0; nt < 8; nt++) {
            int col = nw + nt * 8 + ccol;
            float b0 = bias ? bias[col] : 0.f;
            float b1 = bias ? bias[col + 1] : 0.f;
            float v0 = acc[mt][nt][0] + b0;
            float v1 = acc[mt][nt][1] + b1;
            float v2 = acc[mt][nt][2] + b0;
            float v3 = acc[mt][nt][3] + b1;
            if (r0 < N_NODES) {
                float* p = O + r0 * C + col;
                if (add_prev) { float2 pv = *(float2*)p; v0 += pv.x; v1 += pv.y; }
                if (relu) { v0 = fmaxf(v0, 0.f); v1 = fmaxf(v1, 0.f); }
                *(float2*)p = make_float2(v0, v1);
            }
            if (r1 < N_NODES) {
                float* p = O + r1 * C + col;
                if (add_prev) { float2 pv = *(float2*)p; v2 += pv.x; v3 += pv.y; }
                if (relu) { v2 = fmaxf(v2, 0.f); v3 = fmaxf(v3, 0.f); }
                *(float2*)p = make_float2(v2, v3);
            }
        }
    }
}

// ---------------- launch: fork-join over two streams ----------------
extern "C" void kernel_launch(void* const* d_in, const int* in_sizes, int n_in,
                              void* d_out, int out_size) {
    const float* x    = (const float*)d_in[0];
    const void*  ei   = d_in[1];
    const float* Wl1  = (const float*)d_in[2];
    const float* bl1  = (const float*)d_in[3];
    const float* Wr1  = (const float*)d_in[4];
    const float* Wl2  = (const float*)d_in[5];
    const float* bl2  = (const float*)d_in[6];
    const float* Wr2  = (const float*)d_in[7];
    float* out = (float*)d_out;

    int E = in_sizes[1] / 2;
    if (E > E_CAP) E = E_CAP;

    int node_blocks  = (N_NODES + 255) / 256;
    int edge4_blocks = (E + 1023) / 1024;
    int agg_blocks   = ((N_NODES * 32) + 255) / 256;
    int gemm_blocks  = (N_NODES + 127) / 128;
    int wprep_blocks = (4 * (C * C / 4) + 255) / 256;

    long long total_words_min = (long long)E * 2;
    int nwords = (int)(total_words_min < 8192 ? total_words_min : 8192);

    // One-time host resources (created on the uncaptured correctness call;
    // reused identically on every subsequent call — GPU work is unchanged).
    static cudaStream_t s2 = nullptr;
    static cudaEvent_t ev0 = nullptr, ev1 = nullptr, ev2 = nullptr, ev3 = nullptr;
    if (s2 == nullptr) {
        cudaStreamCreateWithFlags(&s2, cudaStreamNonBlocking);
        cudaEventCreateWithFlags(&ev0, cudaEventDisableTiming);
        cudaEventCreateWithFlags(&ev1, cudaEventDisableTiming);
        cudaEventCreateWithFlags(&ev2, cudaEventDisableTiming);
        cudaEventCreateWithFlags(&ev3, cudaEventDisableTiming);
    }

    // ---- fork: s2 branches off the main (default) stream ----
    cudaEventRecord(ev0, 0);
    cudaStreamWaitEvent(s2, ev0, 0);

    // main stream: CSR build + agg1
    detect_init_kernel<<<node_blocks, 256>>>((const unsigned int*)ei, nwords);
    count_kernel<<<edge4_blocks, 256>>>(ei, E);
    scanA_kernel<<<SCAN_NB, SCAN_BLK>>>();
    scanB_kernel<<<1, 64>>>();
    scanC_kernel<<<SCAN_NB, SCAN_BLK>>>();
    fill_kernel<<<edge4_blocks, 256>>>(ei, E);
    agg_kernel<<<agg_blocks, 256>>>(x, 0);

    // s2: weight prep + gemmWr1: g_h = x @ Wr1^T + bl1 (no relu yet)
    wprep_kernel<<<wprep_blocks, 256, 0, s2>>>(Wl1, Wr1, Wl2, Wr2);
    hmma_half<<<gemm_blocks, 256, 0, s2>>>(x, 0, 1, bl1, nullptr, 1, 0, 0);

    // join: gemmWl1 needs agg1 (main order) + gemmWr1 (ev1)
    cudaEventRecord(ev1, s2);
    cudaStreamWaitEvent(0, ev1, 0);
    // g_h += mean @ Wl1^T ; relu
    hmma_half<<<gemm_blocks, 256>>>(nullptr, 1, 0, nullptr, nullptr, 1, 1, 1);

    // fork: g_h ready
    cudaEventRecord(ev2, 0);
    cudaStreamWaitEvent(s2, ev2, 0);

    // main: agg2 = mean(g_h) ; s2: out = h @ Wr2^T + bl2
    agg_kernel<<<agg_blocks, 256>>>(nullptr, 1);
    hmma_half<<<gemm_blocks, 256, 0, s2>>>(nullptr, 2, 3, bl2, out, 0, 0, 0);

    // join: gemmWl2 needs agg2 (main order) + gemmWr2 (ev3)
    cudaEventRecord(ev3, s2);
    cudaStreamWaitEvent(0, ev3, 0);
    // out += mean @ Wl2^T
    hmma_half<<<gemm_blocks, 256>>>(nullptr, 1, 2, nullptr, out, 0, 1, 0);
}

// round 16
// speedup vs baseline: 1.1313x; 1.1313x over previous
#include <cuda_runtime.h>
#include <cuda_bf16.h>
#include <cstdint>

#define N_NODES 50000
#define C 128
#define C4 32        // float4 per row
#define E_CAP 600064

// ---------------- device scratch (no allocs allowed) ----------------
__device__ __align__(16) float g_agg[(size_t)N_NODES * C];  // mean after agg
__device__ __align__(16) float g_h[(size_t)N_NODES * C];
__device__ __align__(16) float g_inv[N_NODES];
__device__ __align__(16) int   g_cnt[N_NODES];
__device__ __align__(16) int   g_row[N_NODES + 4];
__device__ __align__(16) int   g_cur[N_NODES];
__device__ int g_csr[E_CAP];
__device__ int g_not64 = 0;   // idempotent: set iff int32 evidence found
// preconverted split-bf16 weights: order Wl1, Wr1, Wl2, Wr2
__device__ __align__(16) uint16_t g_wh[4][C * C];
__device__ __align__(16) uint16_t g_wl[4][C * C];
// multi-block scan scratch
#define NCH 12500                 // 50000 / 4 int4 chunks
#define SCAN_BLK 256
#define SCAN_NB ((NCH + SCAN_BLK - 1) / SCAN_BLK)   // 49
__device__ int g_bsum[SCAN_NB];
__device__ int g_boff[SCAN_NB];

__device__ __forceinline__ uint32_t pack_bf(float a, float b) {
    __nv_bfloat162 h = __floats2bfloat162_rn(a, b);  // .x = a (low half)
    return *(uint32_t*)&h;
}

// ============= zero counts + dtype detect =============
__global__ void detect_init_kernel(const unsigned int* __restrict__ w, int nwords) {
    int i = blockIdx.x * blockDim.x + threadIdx.x;
    if (i < N_NODES) g_cnt[i] = 0;
    int wi = 2 * i + 1;
    if (wi < nwords && w[wi] != 0u) g_not64 = 1;
}

// ============= histogram of dst (4 edges/thread, ILP) =============
__global__ void count_kernel(const void* __restrict__ ei, int E) {
    int base = (blockIdx.x * blockDim.x + threadIdx.x) * 4;
    if (base >= E) return;
    int d[4];
    int n = E - base; if (n > 4) n = 4;
    if (g_not64 == 0) {
        const long long* p = (const long long*)ei;
#pragma unroll
        for (int q = 0; q < 4; q++)
            if (q < n) d[q] = (int)p[(long long)E + base + q];
    } else {
        const int* p = (const int*)ei;
#pragma unroll
        for (int q = 0; q < 4; q++)
            if (q < n) d[q] = p[E + base + q];
    }
#pragma unroll
    for (int q = 0; q < 4; q++)
        if (q < n) atomicAdd(&g_cnt[d[q]], 1);
}

// ============= scan A/B/C =============
__global__ __launch_bounds__(SCAN_BLK)
void scanA_kernel() {
    __shared__ int warp_tot[8];
    int tid  = threadIdx.x;
    int lane = tid & 31;
    int wid  = tid >> 5;
    int i = blockIdx.x * SCAN_BLK + tid;
    int4 c = (i < NCH) ? ((const int4*)g_cnt)[i] : make_int4(0, 0, 0, 0);
    int s = c.x + c.y + c.z + c.w;
    int x = s;
#pragma unroll
    for (int off = 1; off < 32; off <<= 1) {
        int y = __shfl_up_sync(0xffffffffu, x, off);
        if (lane >= off) x += y;
    }
    if (lane == 31) warp_tot[wid] = x;
    __syncthreads();
    if (wid == 0 && lane < 8) {
        int t = warp_tot[lane];
        int tx = t;
#pragma unroll
        for (int off = 1; off < 8; off <<= 1) {
            int y = __shfl_up_sync(0xffu, tx, off);
            if (lane >= off) tx += y;
        }
        warp_tot[lane] = tx - t;
    }
    __syncthreads();
    int excl = warp_tot[wid] + x - s;
    if (i < NCH) {
        int4 r;
        r.x = excl;
        r.y = excl + c.x;
        r.z = r.y + c.y;
        r.w = r.z + c.z;
        ((int4*)g_row)[i] = r;
        float4 f;
        f.x = 1.0f / fmaxf((float)c.x, 1.0f);
        f.y = 1.0f / fmaxf((float)c.y, 1.0f);
        f.z = 1.0f / fmaxf((float)c.z, 1.0f);
        f.w = 1.0f / fmaxf((float)c.w, 1.0f);
        ((float4*)g_inv)[i] = f;
    }
    if (tid == SCAN_BLK - 1) g_bsum[blockIdx.x] = excl + s;
}

__global__ void scanB_kernel() {
    __shared__ int sh[2];
    int tid = threadIdx.x;  // 64
    int v = (tid < SCAN_NB) ? g_bsum[tid] : 0;
    int lane = tid & 31, w = tid >> 5;
    int x = v;
#pragma unroll
    for (int off = 1; off < 32; off <<= 1) {
        int y = __shfl_up_sync(0xffffffffu, x, off);
        if (lane >= off) x += y;
    }
    if (lane == 31) sh[w] = x;
    __syncthreads();
    int carry = (w == 1) ? sh[0] : 0;
    int excl = carry + x - v;
    if (tid < SCAN_NB) g_boff[tid] = excl;
    if (tid == SCAN_NB - 1) g_row[N_NODES] = excl + v;
}

__global__ __launch_bounds__(SCAN_BLK)
void scanC_kernel() {
    int i = blockIdx.x * SCAN_BLK + threadIdx.x;
    if (i >= NCH) return;
    int off = g_boff[blockIdx.x];
    int4 r = ((const int4*)g_row)[i];
    r.x += off; r.y += off; r.z += off; r.w += off;
    ((int4*)g_row)[i] = r;
    ((int4*)g_cur)[i] = r;
}

// ============= fill CSR (4 edges/thread, ILP) =============
__global__ void fill_kernel(const void* __restrict__ ei, int E) {
    int base = (blockIdx.x * blockDim.x + threadIdx.x) * 4;
    if (base >= E) return;
    int n = E - base; if (n > 4) n = 4;
    int s[4], d[4];
    if (g_not64 == 0) {
        const long long* p = (const long long*)ei;
#pragma unroll
        for (int q = 0; q < 4; q++)
            if (q < n) {
                s[q] = (int)p[base + q];
                d[q] = (int)p[(long long)E + base + q];
            }
    } else {
        const int* p = (const int*)ei;
#pragma unroll
        for (int q = 0; q < 4; q++)
            if (q < n) {
                s[q] = p[base + q];
                d[q] = p[E + base + q];
            }
    }
    int pos[4];
#pragma unroll
    for (int q = 0; q < 4; q++)
        if (q < n) pos[q] = atomicAdd(&g_cur[d[q]], 1);
#pragma unroll
    for (int q = 0; q < 4; q++)
        if (q < n) g_csr[pos[q]] = s[q];
}

// ============= weight prep: fp32 -> split bf16 =============
__global__ void wprep_kernel(const float* __restrict__ W0, const float* __restrict__ W1,
                             const float* __restrict__ W2, const float* __restrict__ W3) {
    int i = blockIdx.x * blockDim.x + threadIdx.x;
    if (i >= 4 * (C * C / 4)) return;
    int m = i >> 12;
    int q = i & 4095;
    const float* W = (m == 0) ? W0 : (m == 1) ? W1 : (m == 2) ? W2 : W3;
    float4 v = ((const float4*)W)[q];
    float hx = __bfloat162float(__float2bfloat16_rn(v.x));
    float hy = __bfloat162float(__float2bfloat16_rn(v.y));
    float hz = __bfloat162float(__float2bfloat16_rn(v.z));
    float hw = __bfloat162float(__float2bfloat16_rn(v.w));
    *(uint2*)&g_wh[m][q * 4] = make_uint2(pack_bf(hx, hy), pack_bf(hz, hw));
    *(uint2*)&g_wl[m][q * 4] = make_uint2(pack_bf(v.x - hx, v.y - hy),
                                          pack_bf(v.z - hz, v.w - hw));
}

// ============= mean aggregation (gather, no atomics) =============
__global__ __launch_bounds__(256)
void agg_kernel(const float* __restrict__ feat_in, int feat_is_gh) {
    const float* feat = feat_is_gh ? (const float*)g_h : feat_in;
    int gt   = blockIdx.x * blockDim.x + threadIdx.x;
    int node = gt >> 5;
    int lane = gt & 31;
    if (node >= N_NODES) return;
    int beg = g_row[node];
    int end = g_row[node + 1];
    const float4* f4 = (const float4*)feat;
    float4 acc = make_float4(0.f, 0.f, 0.f, 0.f);
    int i = beg;
    for (; i + 4 <= end; i += 4) {
        int s0 = g_csr[i + 0];
        int s1 = g_csr[i + 1];
        int s2 = g_csr[i + 2];
        int s3 = g_csr[i + 3];
        float4 v0 = f4[(size_t)s0 * C4 + lane];
        float4 v1 = f4[(size_t)s1 * C4 + lane];
        float4 v2 = f4[(size_t)s2 * C4 + lane];
        float4 v3 = f4[(size_t)s3 * C4 + lane];
        acc.x += v0.x + v1.x + v2.x + v3.x;
        acc.y += v0.y + v1.y + v2.y + v3.y;
        acc.z += v0.z + v1.z + v2.z + v3.z;
        acc.w += v0.w + v1.w + v2.w + v3.w;
    }
    for (; i < end; i++) {
        float4 v = f4[(size_t)g_csr[i] * C4 + lane];
        acc.x += v.x; acc.y += v.y; acc.z += v.z; acc.w += v.w;
    }
    float inv = g_inv[node];
    acc.x *= inv; acc.y *= inv; acc.z *= inv; acc.w *= inv;
    ((float4*)g_agg)[(size_t)node * C4 + lane] = acc;
}

// ============= bf16-split fused SAGE layer, M-tile 64 =============
// One CTA = 64 output rows x 128 cols.  8 warps: 2 over m (32 rows),
// 4 over n (32 cols).  chunks 0..3: A = mean (g_agg), B = Wl;
// chunks 4..7: A = xin, B = Wr.  D += Ah*Bh + Ah*Bl + Al*Bh (fp32 accum).
#define SA 40   // padded row length (bf16 elems)

__device__ __forceinline__ uint32_t smem_u32(const void* p) {
    uint32_t a;
    asm("{ .reg .u64 t; cvta.to.shared.u64 t, %1; cvt.u32.u64 %0, t; }"
        : "=r"(a) : "l"(p));
    return a;
}

__device__ __forceinline__ void ldm_x4(uint32_t* r, uint32_t addr) {
    asm volatile("ldmatrix.sync.aligned.m8n8.x4.shared.b16 {%0,%1,%2,%3}, [%4];"
                 : "=r"(r[0]), "=r"(r[1]), "=r"(r[2]), "=r"(r[3]) : "r"(addr));
}

__device__ __forceinline__ void mma_bf16(float* d, const uint32_t* a,
                                         uint32_t b0, uint32_t b1) {
    asm volatile(
        "mma.sync.aligned.m16n8k16.row.col.f32.bf16.bf16.f32 "
        "{%0,%1,%2,%3}, {%4,%5,%6,%7}, {%8,%9}, {%0,%1,%2,%3};"
        : "+f"(d[0]), "+f"(d[1]), "+f"(d[2]), "+f"(d[3])
        : "r"(a[0]), "r"(a[1]), "r"(a[2]), "r"(a[3]), "r"(b0), "r"(b1));
}

__global__ __launch_bounds__(256)
void hmma_gemm(const float* __restrict__ xin, int x_is_gh, int layer,
               const float* __restrict__ bias,
               float* __restrict__ Oin, int o_is_gh, int relu) {
    __shared__ __align__(16) uint16_t sAh[64 * SA];
    __shared__ __align__(16) uint16_t sAl[64 * SA];
    __shared__ __align__(16) uint16_t sBh[128 * SA];
    __shared__ __align__(16) uint16_t sBl[128 * SA];

    const float* A2 = x_is_gh ? (const float*)g_h : xin;
    float*       O  = o_is_gh ? (float*)g_h : Oin;

    int t    = threadIdx.x;
    int w    = t >> 5;
    int lane = t & 31;
    int mw   = (w & 1) * 32;    // 2 warp-groups over m
    int nw   = (w >> 1) * 32;   // 4 warp-groups over n
    long long bm = (long long)blockIdx.x * 64;

    float acc[2][4][4];
#pragma unroll
    for (int i = 0; i < 2; i++)
#pragma unroll
        for (int j = 0; j < 4; j++)
#pragma unroll
            for (int q = 0; q < 4; q++) acc[i][j][q] = 0.f;

    uint32_t aAh = smem_u32(sAh), aAl = smem_u32(sAl);
    uint32_t aBh = smem_u32(sBh), aBl = smem_u32(sBl);

    // A loader: row = t>>2 (0..63), 8 cols starting at (t&3)*8
    int alrow = t >> 2;
    int alq   = t & 3;
    long long arow = bm + alrow;
    if (arow >= N_NODES) arow = N_NODES - 1;
    int acb = alrow * SA + alq * 8;
    // B loader: row = t>>1 (0..127), 16 cols at (t&1)*16
    int blrow = t >> 1;
    int blhk  = t & 1;
    int bcb = blrow * SA + blhk * 16;

#pragma unroll 1
    for (int chunk = 0; chunk < 8; chunk++) {
        int phase = chunk >> 2;
        int k0    = (chunk & 3) * 32;

        // ---- A: load fp32 (2 float4 = 8 cols), split-convert to smem ----
        const float4* asrc = (const float4*)(phase ? A2 : (const float*)g_agg);
        const float4* pa = asrc + arow * C4 + (k0 >> 2) + alq * 2;
#pragma unroll
        for (int q = 0; q < 2; q++) {
            float4 v = pa[q];
            float hx = __bfloat162float(__float2bfloat16_rn(v.x));
            float hy = __bfloat162float(__float2bfloat16_rn(v.y));
            float hz = __bfloat162float(__float2bfloat16_rn(v.z));
            float hw = __bfloat162float(__float2bfloat16_rn(v.w));
            *(uint32_t*)&sAh[acb + q * 4]     = pack_bf(hx, hy);
            *(uint32_t*)&sAh[acb + q * 4 + 2] = pack_bf(hz, hw);
            *(uint32_t*)&sAl[acb + q * 4]     = pack_bf(v.x - hx, v.y - hy);
            *(uint32_t*)&sAl[acb + q * 4 + 2] = pack_bf(v.z - hz, v.w - hw);
        }
        // ---- B: bf16 copies from preconverted weights ----
        {
            const uint4* ph = (const uint4*)&g_wh[2 * layer + phase][blrow * C + k0 + blhk * 16];
            const uint4* pl = (const uint4*)&g_wl[2 * layer + phase][blrow * C + k0 + blhk * 16];
            *(uint4*)&sBh[bcb]     = ph[0];
            *(uint4*)&sBh[bcb + 8] = ph[1];
            *(uint4*)&sBl[bcb]     = pl[0];
            *(uint4*)&sBl[bcb + 8] = pl[1];
        }
        __syncthreads();

        // ---- MMA over the 32-K chunk (two k16 halves) ----
#pragma unroll
        for (int k16 = 0; k16 < 2; k16++) {
            int kb = k16 * 16;
            uint32_t ah[2][4], al[2][4];
#pragma unroll
            for (int mt = 0; mt < 2; mt++) {
                int off = ((mw + mt * 16 + (lane & 15)) * SA
                           + kb + (lane >> 4) * 8) * 2;
                ldm_x4(ah[mt], aAh + off);
                ldm_x4(al[mt], aAl + off);
            }
            uint32_t bh[2][4], bl[2][4];
#pragma unroll
            for (int g = 0; g < 2; g++) {
                int row = nw + g * 16 + (lane & 7) + ((lane >> 3) & 1) * 8;
                int col = kb + ((lane >> 4) & 1) * 8;
                int off = (row * SA + col) * 2;
                ldm_x4(bh[g], aBh + off);
                ldm_x4(bl[g], aBl + off);
            }
#pragma unroll
            for (int mt = 0; mt < 2; mt++) {
#pragma unroll
                for (int nt = 0; nt < 4; nt++) {
                    int g = nt >> 1, s = nt & 1;
                    uint32_t bh0 = bh[g][s], bh1 = bh[g][s + 2];
                    uint32_t bl0 = bl[g][s], bl1 = bl[g][s + 2];
                    mma_bf16(acc[mt][nt], ah[mt], bh0, bh1);  // hi*hi
                    mma_bf16(acc[mt][nt], ah[mt], bl0, bl1);  // hi*lo
                    mma_bf16(acc[mt][nt], al[mt], bh0, bh1);  // lo*hi
                }
            }
        }
        __syncthreads();
    }

    // ---- epilogue ----
    int crow = lane >> 2;
    int ccol = (lane & 3) * 2;
#pragma unroll
    for (int mt = 0; mt < 2; mt++) {
        long long r0 = bm + mw + mt * 16 + crow;
        long long r1 = r0 + 8;
#pragma unroll
        for (int nt = 0; nt < 4; nt++) {
            int col = nw + nt * 8 + ccol;
            float b0 = bias[col], b1 = bias[col + 1];
            float v0 = acc[mt][nt][0] + b0;
            float v1 = acc[mt][nt][1] + b1;
            float v2 = acc[mt][nt][2] + b0;
            float v3 = acc[mt][nt][3] + b1;
            if (relu) {
                v0 = fmaxf(v0, 0.f); v1 = fmaxf(v1, 0.f);
                v2 = fmaxf(v2, 0.f); v3 = fmaxf(v3, 0.f);
            }
            if (r0 < N_NODES) *(float2*)(O + r0 * C + col) = make_float2(v0, v1);
            if (r1 < N_NODES) *(float2*)(O + r1 * C + col) = make_float2(v2, v3);
        }
    }
}

// ---------------- launch (single stream, R11 topology) ----------------
extern "C" void kernel_launch(void* const* d_in, const int* in_sizes, int n_in,
                              void* d_out, int out_size) {
    const float* x    = (const float*)d_in[0];
    const void*  ei   = d_in[1];
    const float* Wl1  = (const float*)d_in[2];
    const float* bl1  = (const float*)d_in[3];
    const float* Wr1  = (const float*)d_in[4];
    const float* Wl2  = (const float*)d_in[5];
    const float* bl2  = (const float*)d_in[6];
    const float* Wr2  = (const float*)d_in[7];
    float* out = (float*)d_out;

    int E = in_sizes[1] / 2;
    if (E > E_CAP) E = E_CAP;

    int node_blocks  = (N_NODES + 255) / 256;
    int edge4_blocks = (E + 1023) / 1024;
    int agg_blocks   = ((N_NODES * 32) + 255) / 256;
    int gemm_blocks  = (N_NODES + 63) / 64;        // 782
    int wprep_blocks = (4 * (C * C / 4) + 255) / 256;

    long long total_words_min = (long long)E * 2;
    int nwords = (int)(total_words_min < 8192 ? total_words_min : 8192);

    // CSR build + weight prep
    detect_init_kernel<<<node_blocks, 256>>>((const unsigned int*)ei, nwords);
    count_kernel<<<edge4_blocks, 256>>>(ei, E);
    scanA_kernel<<<SCAN_NB, SCAN_BLK>>>();
    scanB_kernel<<<1, 64>>>();
    scanC_kernel<<<SCAN_NB, SCAN_BLK>>>();
    fill_kernel<<<edge4_blocks, 256>>>(ei, E);
    wprep_kernel<<<wprep_blocks, 256>>>(Wl1, Wr1, Wl2, Wr2);

    // layer 1: mean(x) -> g_agg ; g_h = relu(mean@Wl1^T + bl1 + x@Wr1^T)
    agg_kernel<<<agg_blocks, 256>>>(x, 0);
    hmma_gemm<<<gemm_blocks, 256>>>(x, 0, 0, bl1, nullptr, 1, 1);

    // layer 2: mean(h) -> g_agg ; out = mean@Wl2^T + bl2 + h@Wr2^T
    agg_kernel<<<agg_blocks, 256>>>(nullptr, 1);
    hmma_gemm<<<gemm_blocks, 256>>>(nullptr, 1, 1, bl2, out, 0, 0);
}

// round 17
// speedup vs baseline: 1.2026x; 1.0631x over previous
#include <cuda_runtime.h>
#include <cuda_bf16.h>
#include <cstdint>

#define N_NODES 50000
#define C 128
#define C4 32        // float4 per row
#define E_CAP 600064

// ---------------- device scratch (no allocs allowed) ----------------
__device__ __align__(16) float g_agg[(size_t)N_NODES * C];  // mean after agg
__device__ __align__(16) float g_h[(size_t)N_NODES * C];
__device__ __align__(16) float g_inv[N_NODES];
__device__ __align__(16) int   g_cnt[N_NODES];   // zero-init; scanA re-zeros
__device__ __align__(16) int   g_row[N_NODES + 4];
__device__ __align__(16) int   g_cur[N_NODES];
__device__ int g_csr[E_CAP];
// preconverted split-bf16 weights: order Wl1, Wr1, Wl2, Wr2
__device__ __align__(16) uint16_t g_wh[4][C * C];
__device__ __align__(16) uint16_t g_wl[4][C * C];
// multi-block scan scratch
#define NCH 12500                 // 50000 / 4 int4 chunks
#define SCAN_BLK 256
#define SCAN_NB ((NCH + SCAN_BLK - 1) / SCAN_BLK)   // 49
__device__ int g_bsum[SCAN_NB];

__device__ __forceinline__ uint32_t pack_bf(float a, float b) {
    __nv_bfloat162 h = __floats2bfloat162_rn(a, b);  // .x = a (low half)
    return *(uint32_t*)&h;
}

// Per-block dtype detect: warp 0 ballots the first 32 odd 32-bit words.
// int64 indices in [0,50000) -> all high words zero -> ballot 0 -> int64.
// int32 data -> those words are random src indices -> ballot nonzero.
__device__ __forceinline__ int block_detect_not64(const unsigned int* w,
                                                  int* s_flag) {
    int tid = threadIdx.x;
    if (tid < 32) {
        unsigned v = w[2 * tid + 1];
        unsigned any = __ballot_sync(0xffffffffu, v != 0u);
        if (tid == 0) *s_flag = (any != 0u);
    }
    __syncthreads();
    return *s_flag;
}

// ============= launch 1: histogram of dst + inline wprep =============
// 4 edges/thread (ILP over ~318-cyc ATOMG latency). Blocks 0..63 also
// convert the 4 weight matrices to split-bf16 (independent side work).
__global__ void count_kernel(const void* __restrict__ ei, int E,
                             const float* __restrict__ W0, const float* __restrict__ W1,
                             const float* __restrict__ W2, const float* __restrict__ W3) {
    __shared__ int s_not64;
    int not64 = block_detect_not64((const unsigned int*)ei, &s_not64);
    int tid = threadIdx.x;

    // inline weight prep (blocks 0..63 cover 4 * 4096 float4s)
    if (blockIdx.x < 64) {
        int i = blockIdx.x * 256 + tid;
        int m = i >> 12;
        int q = i & 4095;
        const float* W = (m == 0) ? W0 : (m == 1) ? W1 : (m == 2) ? W2 : W3;
        float4 v = ((const float4*)W)[q];
        float hx = __bfloat162float(__float2bfloat16_rn(v.x));
        float hy = __bfloat162float(__float2bfloat16_rn(v.y));
        float hz = __bfloat162float(__float2bfloat16_rn(v.z));
        float hw = __bfloat162float(__float2bfloat16_rn(v.w));
        *(uint2*)&g_wh[m][q * 4] = make_uint2(pack_bf(hx, hy), pack_bf(hz, hw));
        *(uint2*)&g_wl[m][q * 4] = make_uint2(pack_bf(v.x - hx, v.y - hy),
                                              pack_bf(v.z - hz, v.w - hw));
    }

    int base = (blockIdx.x * blockDim.x + tid) * 4;
    if (base >= E) return;
    int d[4];
    int n = E - base; if (n > 4) n = 4;
    if (not64 == 0) {
        const long long* p = (const long long*)ei;
#pragma unroll
        for (int q = 0; q < 4; q++)
            if (q < n) d[q] = (int)p[(long long)E + base + q];
    } else {
        const int* p = (const int*)ei;
#pragma unroll
        for (int q = 0; q < 4; q++)
            if (q < n) d[q] = p[E + base + q];
    }
#pragma unroll
    for (int q = 0; q < 4; q++)
        if (q < n) atomicAdd(&g_cnt[d[q]], 1);
}

// ============= launch 2: per-block partial scan; re-zeros g_cnt =============
__global__ __launch_bounds__(SCAN_BLK)
void scanA_kernel() {
    __shared__ int warp_tot[8];
    int tid  = threadIdx.x;
    int lane = tid & 31;
    int wid  = tid >> 5;
    int i = blockIdx.x * SCAN_BLK + tid;
    int4 c = (i < NCH) ? ((const int4*)g_cnt)[i] : make_int4(0, 0, 0, 0);
    if (i < NCH) ((int4*)g_cnt)[i] = make_int4(0, 0, 0, 0);  // reset for next run
    int s = c.x + c.y + c.z + c.w;
    int x = s;
#pragma unroll
    for (int off = 1; off < 32; off <<= 1) {
        int y = __shfl_up_sync(0xffffffffu, x, off);
        if (lane >= off) x += y;
    }
    if (lane == 31) warp_tot[wid] = x;
    __syncthreads();
    if (wid == 0 && lane < 8) {
        int t = warp_tot[lane];
        int tx = t;
#pragma unroll
        for (int off = 1; off < 8; off <<= 1) {
            int y = __shfl_up_sync(0xffu, tx, off);
            if (lane >= off) tx += y;
        }
        warp_tot[lane] = tx - t;
    }
    __syncthreads();
    int excl = warp_tot[wid] + x - s;
    if (i < NCH) {
        int4 r;
        r.x = excl;
        r.y = excl + c.x;
        r.z = r.y + c.y;
        r.w = r.z + c.z;
        ((int4*)g_row)[i] = r;
        float4 f;
        f.x = 1.0f / fmaxf((float)c.x, 1.0f);
        f.y = 1.0f / fmaxf((float)c.y, 1.0f);
        f.z = 1.0f / fmaxf((float)c.z, 1.0f);
        f.w = 1.0f / fmaxf((float)c.w, 1.0f);
        ((float4*)g_inv)[i] = f;
    }
    if (tid == SCAN_BLK - 1) g_bsum[blockIdx.x] = excl + s;
}

// ============= launch 3: block-offset prefix (redundant per block) + apply ==
__global__ __launch_bounds__(SCAN_BLK)
void scanBC_kernel() {
    __shared__ int sh_warp[2];
    __shared__ int s_off, s_tot;
    int tid  = threadIdx.x;
    int lane = tid & 31;
    int wq   = tid >> 5;
    int v = 0, x = 0;
    if (tid < 64) {
        v = (tid < SCAN_NB) ? g_bsum[tid] : 0;
        x = v;
#pragma unroll
        for (int off = 1; off < 32; off <<= 1) {
            int y = __shfl_up_sync(0xffffffffu, x, off);
            if (lane >= off) x += y;
        }
        if (lane == 31) sh_warp[wq] = x;
    }
    __syncthreads();
    if (tid < 64) {
        int carry = (wq == 1) ? sh_warp[0] : 0;
        int excl = carry + x - v;
        if (tid == (int)blockIdx.x) s_off = excl;
        if (tid == SCAN_NB - 1) s_tot = excl + v;
    }
    __syncthreads();
    int off = s_off;
    int i = blockIdx.x * SCAN_BLK + tid;
    if (i < NCH) {
        int4 r = ((const int4*)g_row)[i];
        r.x += off; r.y += off; r.z += off; r.w += off;
        ((int4*)g_row)[i] = r;
        ((int4*)g_cur)[i] = r;
    }
    if (blockIdx.x == SCAN_NB - 1 && tid == 0) g_row[N_NODES] = s_tot;
}

// ============= launch 4: fill CSR (4 edges/thread, inline detect) ===========
__global__ void fill_kernel(const void* __restrict__ ei, int E) {
    __shared__ int s_not64;
    int not64 = block_detect_not64((const unsigned int*)ei, &s_not64);
    int base = (blockIdx.x * blockDim.x + threadIdx.x) * 4;
    if (base >= E) return;
    int n = E - base; if (n > 4) n = 4;
    int s[4], d[4];
    if (not64 == 0) {
        const long long* p = (const long long*)ei;
#pragma unroll
        for (int q = 0; q < 4; q++)
            if (q < n) {
                s[q] = (int)p[base + q];
                d[q] = (int)p[(long long)E + base + q];
            }
    } else {
        const int* p = (const int*)ei;
#pragma unroll
        for (int q = 0; q < 4; q++)
            if (q < n) {
                s[q] = p[base + q];
                d[q] = p[E + base + q];
            }
    }
    int pos[4];
#pragma unroll
    for (int q = 0; q < 4; q++)
        if (q < n) pos[q] = atomicAdd(&g_cur[d[q]], 1);
#pragma unroll
    for (int q = 0; q < 4; q++)
        if (q < n) g_csr[pos[q]] = s[q];
}

// ============= mean aggregation (gather, no atomics) =============
__global__ __launch_bounds__(256)
void agg_kernel(const float* __restrict__ feat_in, int feat_is_gh) {
    const float* feat = feat_is_gh ? (const float*)g_h : feat_in;
    int gt   = blockIdx.x * blockDim.x + threadIdx.x;
    int node = gt >> 5;
    int lane = gt & 31;
    if (node >= N_NODES) return;
    int beg = g_row[node];
    int end = g_row[node + 1];
    const float4* f4 = (const float4*)feat;
    float4 acc = make_float4(0.f, 0.f, 0.f, 0.f);
    int i = beg;
    for (; i + 4 <= end; i += 4) {
        int s0 = g_csr[i + 0];
        int s1 = g_csr[i + 1];
        int s2 = g_csr[i + 2];
        int s3 = g_csr[i + 3];
        float4 v0 = f4[(size_t)s0 * C4 + lane];
        float4 v1 = f4[(size_t)s1 * C4 + lane];
        float4 v2 = f4[(size_t)s2 * C4 + lane];
        float4 v3 = f4[(size_t)s3 * C4 + lane];
        acc.x += v0.x + v1.x + v2.x + v3.x;
        acc.y += v0.y + v1.y + v2.y + v3.y;
        acc.z += v0.z + v1.z + v2.z + v3.z;
        acc.w += v0.w + v1.w + v2.w + v3.w;
    }
    for (; i < end; i++) {
        float4 v = f4[(size_t)g_csr[i] * C4 + lane];
        acc.x += v.x; acc.y += v.y; acc.z += v.z; acc.w += v.w;
    }
    float inv = g_inv[node];
    acc.x *= inv; acc.y *= inv; acc.z *= inv; acc.w *= inv;
    ((float4*)g_agg)[(size_t)node * C4 + lane] = acc;
}

// ============= bf16-split fused SAGE layer via mma.sync (R11 M128) ==========
// chunks 0..3: A = mean (g_agg), B = W[2*layer] (Wl)
// chunks 4..7: A = xin,          B = W[2*layer+1] (Wr)
// D += Ah*Bh + Ah*Bl + Al*Bh  (fp32 accum; lo*lo dropped)
#define SA 40   // padded row length (bf16 elems) for 128x32 tiles

__device__ __forceinline__ uint32_t smem_u32(const void* p) {
    uint32_t a;
    asm("{ .reg .u64 t; cvta.to.shared.u64 t, %1; cvt.u32.u64 %0, t; }"
        : "=r"(a) : "l"(p));
    return a;
}

__device__ __forceinline__ void ldm_x4(uint32_t* r, uint32_t addr) {
    asm volatile("ldmatrix.sync.aligned.m8n8.x4.shared.b16 {%0,%1,%2,%3}, [%4];"
                 : "=r"(r[0]), "=r"(r[1]), "=r"(r[2]), "=r"(r[3]) : "r"(addr));
}

__device__ __forceinline__ void mma_bf16(float* d, const uint32_t* a,
                                         uint32_t b0, uint32_t b1) {
    asm volatile(
        "mma.sync.aligned.m16n8k16.row.col.f32.bf16.bf16.f32 "
        "{%0,%1,%2,%3}, {%4,%5,%6,%7}, {%8,%9}, {%0,%1,%2,%3};"
        : "+f"(d[0]), "+f"(d[1]), "+f"(d[2]), "+f"(d[3])
        : "r"(a[0]), "r"(a[1]), "r"(a[2]), "r"(a[3]), "r"(b0), "r"(b1));
}

__global__ __launch_bounds__(256)
void hmma_gemm(const float* __restrict__ xin, int x_is_gh, int layer,
               const float* __restrict__ bias,
               float* __restrict__ Oin, int o_is_gh, int relu) {
    __shared__ __align__(16) uint16_t sAh[128 * SA];
    __shared__ __align__(16) uint16_t sAl[128 * SA];
    __shared__ __align__(16) uint16_t sBh[128 * SA];
    __shared__ __align__(16) uint16_t sBl[128 * SA];

    const float* A2 = x_is_gh ? (const float*)g_h : xin;
    float*       O  = o_is_gh ? (float*)g_h : Oin;

    int t    = threadIdx.x;
    int w    = t >> 5;
    int lane = t & 31;
    int mw   = (w & 3) * 32;   // warp m-offset (4 warps over m)
    int nw   = (w >> 2) * 64;  // warp n-offset (2 warps over n)
    long long bm = (long long)blockIdx.x * 128;

    float acc[2][8][4];
#pragma unroll
    for (int i = 0; i < 2; i++)
#pragma unroll
        for (int j = 0; j < 8; j++)
#pragma unroll
            for (int q = 0; q < 4; q++) acc[i][j][q] = 0.f;

    uint32_t aAh = smem_u32(sAh), aAl = smem_u32(sAl);
    uint32_t aBh = smem_u32(sBh), aBl = smem_u32(sBl);

    // loader indices: row = t>>1, half-k = t&1 (16 cols each)
    int lrow = t >> 1;
    int lhk  = t & 1;
    long long arow = bm + lrow;
    if (arow >= N_NODES) arow = N_NODES - 1;
    int cbase = lrow * SA + lhk * 16;

#pragma unroll 1
    for (int chunk = 0; chunk < 8; chunk++) {
        int phase = chunk >> 2;
        int k0    = (chunk & 3) * 32;

        // ---- A: load fp32, split-convert to smem ----
        const float4* asrc = (const float4*)(phase ? A2 : (const float*)g_agg);
        const float4* pa = asrc + arow * C4 + (k0 >> 2) + lhk * 4;
#pragma unroll
        for (int q = 0; q < 4; q++) {
            float4 v = pa[q];
            float hx = __bfloat162float(__float2bfloat16_rn(v.x));
            float hy = __bfloat162float(__float2bfloat16_rn(v.y));
            float hz = __bfloat162float(__float2bfloat16_rn(v.z));
            float hw = __bfloat162float(__float2bfloat16_rn(v.w));
            *(uint32_t*)&sAh[cbase + q * 4]     = pack_bf(hx, hy);
            *(uint32_t*)&sAh[cbase + q * 4 + 2] = pack_bf(hz, hw);
            *(uint32_t*)&sAl[cbase + q * 4]     = pack_bf(v.x - hx, v.y - hy);
            *(uint32_t*)&sAl[cbase + q * 4 + 2] = pack_bf(v.z - hz, v.w - hw);
        }
        // ---- B: straight bf16 copies from preconverted weights ----
        {
            const uint16_t* bh = g_wh[2 * layer + phase];
            const uint16_t* bl = g_wl[2 * layer + phase];
            const uint4* ph = (const uint4*)&bh[lrow * C + k0 + lhk * 16];
            const uint4* pl = (const uint4*)&bl[lrow * C + k0 + lhk * 16];
            *(uint4*)&sBh[cbase]     = ph[0];
            *(uint4*)&sBh[cbase + 8] = ph[1];
            *(uint4*)&sBl[cbase]     = pl[0];
            *(uint4*)&sBl[cbase + 8] = pl[1];
        }
        __syncthreads();

        // ---- MMA over the 32-K chunk (two k16 halves) ----
#pragma unroll
        for (int k16 = 0; k16 < 2; k16++) {
            int kb = k16 * 16;
            uint32_t ah[2][4], al[2][4];
#pragma unroll
            for (int mt = 0; mt < 2; mt++) {
                int off = ((mw + mt * 16 + (lane & 15)) * SA
                           + kb + (lane >> 4) * 8) * 2;
                ldm_x4(ah[mt], aAh + off);
                ldm_x4(al[mt], aAl + off);
            }
            uint32_t bh[4][4], bl[4][4];
#pragma unroll
            for (int g = 0; g < 4; g++) {
                int row = nw + g * 16 + (lane & 7) + ((lane >> 3) & 1) * 8;
                int col = kb + ((lane >> 4) & 1) * 8;
                int off = (row * SA + col) * 2;
                ldm_x4(bh[g], aBh + off);
                ldm_x4(bl[g], aBl + off);
            }
#pragma unroll
            for (int mt = 0; mt < 2; mt++) {
#pragma unroll
                for (int nt = 0; nt < 8; nt++) {
                    int g = nt >> 1, s = nt & 1;
                    uint32_t bh0 = bh[g][s], bh1 = bh[g][s + 2];
                    uint32_t bl0 = bl[g][s], bl1 = bl[g][s + 2];
                    mma_bf16(acc[mt][nt], ah[mt], bh0, bh1);  // hi*hi
                    mma_bf16(acc[mt][nt], ah[mt], bl0, bl1);  // hi*lo
                    mma_bf16(acc[mt][nt], al[mt], bh0, bh1);  // lo*hi
                }
            }
        }
        __syncthreads();
    }

    // ---- epilogue ----
    int crow = lane >> 2;
    int ccol = (lane & 3) * 2;
#pragma unroll
    for (int mt = 0; mt < 2; mt++) {
        long long r0 = bm + mw + mt * 16 + crow;
        long long r1 = r0 + 8;
#pragma unroll
        for (int nt = 0; nt < 8; nt++) {
            int col = nw + nt * 8 + ccol;
            float b0 = bias[col], b1 = bias[col + 1];
            float v0 = acc[mt][nt][0] + b0;
            float v1 = acc[mt][nt][1] + b1;
            float v2 = acc[mt][nt][2] + b0;
            float v3 = acc[mt][nt][3] + b1;
            if (relu) {
                v0 = fmaxf(v0, 0.f); v1 = fmaxf(v1, 0.f);
                v2 = fmaxf(v2, 0.f); v3 = fmaxf(v3, 0.f);
            }
            if (r0 < N_NODES) *(float2*)(O + r0 * C + col) = make_float2(v0, v1);
            if (r1 < N_NODES) *(float2*)(O + r1 * C + col) = make_float2(v2, v3);
        }
    }
}

// ---------------- launch (8 launches, single stream) ----------------
extern "C" void kernel_launch(void* const* d_in, const int* in_sizes, int n_in,
                              void* d_out, int out_size) {
    const float* x    = (const float*)d_in[0];
    const void*  ei   = d_in[1];
    const float* Wl1  = (const float*)d_in[2];
    const float* bl1  = (const float*)d_in[3];
    const float* Wr1  = (const float*)d_in[4];
    const float* Wl2  = (const float*)d_in[5];
    const float* bl2  = (const float*)d_in[6];
    const float* Wr2  = (const float*)d_in[7];
    float* out = (float*)d_out;

    int E = in_sizes[1] / 2;
    if (E > E_CAP) E = E_CAP;

    int edge4_blocks = (E + 1023) / 1024;          // >= 586 (> 64 for wprep)
    int agg_blocks   = ((N_NODES * 32) + 255) / 256;
    int gemm_blocks  = (N_NODES + 127) / 128;      // 391

    // CSR build (wprep + dtype detect folded into count/fill)
    count_kernel<<<edge4_blocks, 256>>>(ei, E, Wl1, Wr1, Wl2, Wr2);
    scanA_kernel<<<SCAN_NB, SCAN_BLK>>>();
    scanBC_kernel<<<SCAN_NB, SCAN_BLK>>>();
    fill_kernel<<<edge4_blocks, 256>>>(ei, E);

    // layer 1: mean(x) -> g_agg ; g_h = relu(mean@Wl1^T + bl1 + x@Wr1^T)
    agg_kernel<<<agg_blocks, 256>>>(x, 0);
    hmma_gemm<<<gemm_blocks, 256>>>(x, 0, 0, bl1, nullptr, 1, 1);

    // layer 2: mean(h) -> g_agg ; out = mean@Wl2^T + bl2 + h@Wr2^T
    agg_kernel<<<agg_blocks, 256>>>(nullptr, 1);
    hmma_gemm<<<gemm_blocks, 256>>>(nullptr, 1, 1, bl2, out, 0, 0);
}